// round 16
// baseline (speedup 1.0000x reference)
#include <cuda_runtime.h>

#define BATCH   32
#define TSTEPS  1024
#define COLS    2048
#define THREADS 128            /* 4 warps, one per SMSP */
#define V       16             /* columns per thread = 4 float4 */
#define NF4     4              /* float4 chunks per thread */
#define WARPS   (THREADS / 32) /* 4 */
#define ROW4    (COLS / 4)     /* row stride in float4 = 512 */
#define DPF     4              /* x prefetch depth (time steps) */

__device__ __forceinline__ float smix(float a, float b) {
    float d = a - b;                       /* a - b          */
    float e = __expf(-d);                  /* MUFU.EX2 path  */
    float p = __fdividef(1.0f, 1.0f + e);  /* MUFU.RCP path  */
    return fmaf(p, d, b);                  /* b + p*(a-b)    */
}

__global__ __launch_bounds__(THREADS, 1)
void softscan_kernel(const float* __restrict__ x, float* __restrict__ out) {
    const int b    = blockIdx.x;           /* one CTA per batch row */
    const int tid  = threadIdx.x;
    const int lane = tid & 31;
    const int warp = tid >> 5;

    __shared__ float sh[2][WARPS];         /* double-buffered warp-seam values */

    /* thread owns 4 contiguous float4s = 16 columns */
    const float4* xp = (const float4*)(x   + (size_t)b * TSTEPS * COLS) + tid * NF4;
    float4*       op = (float4*)      (out + (size_t)b * TSTEPS * COLS) + tid * NF4;

    const bool seamer   = (lane == 31) && (warp != WARPS - 1);
    const bool firstcol = (tid == 0);

    /* ---- t = 0: carry = x[b,0,:] ---- */
    float4 c0 = __ldcs(xp + 0), c1 = __ldcs(xp + 1),
           c2 = __ldcs(xp + 2), c3 = __ldcs(xp + 3);
    __stcs(op + 0, c0); __stcs(op + 1, c1);
    __stcs(op + 2, c2); __stcs(op + 3, c3);
    if (seamer) sh[0][warp] = c3.w;

    /* x prefetch ring: buf[k][i] holds row t where (t-1)&3 == k */
    float4 buf[DPF][NF4];
    #pragma unroll
    for (int k = 0; k < DPF; ++k)
        #pragma unroll
        for (int i = 0; i < NF4; ++i)
            buf[k][i] = __ldcs(xp + (size_t)(k + 1) * ROW4 + i);
    __syncthreads();

    for (int tb = 1; tb < TSTEPS; tb += DPF) {
        #pragma unroll
        for (int k = 0; k < DPF; ++k) {
            const int t = tb + k;          /* (t-1)&3 == k by construction */
            if (t >= TSTEPS) break;

            float4 xv0 = buf[k][0], xv1 = buf[k][1],
                   xv2 = buf[k][2], xv3 = buf[k][3];
            if (t + DPF < TSTEPS) {
                #pragma unroll
                for (int i = 0; i < NF4; ++i)
                    buf[k][i] = __ldcs(xp + (size_t)(t + DPF) * ROW4 + i);
            }

            /* left neighbor's carry (this thread's col-1) from step t-1 */
            float left = __shfl_up_sync(0xffffffffu, c3.w, 1);
            if (lane == 0 && warp > 0)
                left = sh[(t - 1) & 1][warp - 1];

            /* 16 independent mixes, all reading OLD carries */
            float4 n0, n1, n2, n3;
            n0.x = firstcol ? (xv0.x + c0.x) : (xv0.x + smix(c0.x, left));
            n0.y = xv0.y + smix(c0.y, c0.x);
            n0.z = xv0.z + smix(c0.z, c0.y);
            n0.w = xv0.w + smix(c0.w, c0.z);
            n1.x = xv1.x + smix(c1.x, c0.w);
            n1.y = xv1.y + smix(c1.y, c1.x);
            n1.z = xv1.z + smix(c1.z, c1.y);
            n1.w = xv1.w + smix(c1.w, c1.z);
            n2.x = xv2.x + smix(c2.x, c1.w);
            n2.y = xv2.y + smix(c2.y, c2.x);
            n2.z = xv2.z + smix(c2.z, c2.y);
            n2.w = xv2.w + smix(c2.w, c2.z);
            n3.x = xv3.x + smix(c3.x, c2.w);
            n3.y = xv3.y + smix(c3.y, c3.x);
            n3.z = xv3.z + smix(c3.z, c3.y);
            n3.w = xv3.w + smix(c3.w, c3.z);
            c0 = n0; c1 = n1; c2 = n2; c3 = n3;

            float4* o = op + (size_t)t * ROW4;
            __stcs(o + 0, c0); __stcs(o + 1, c1);
            __stcs(o + 2, c2); __stcs(o + 3, c3);
            if (seamer) sh[t & 1][warp] = c3.w;
            __syncthreads();
        }
    }
}

extern "C" void kernel_launch(void* const* d_in, const int* in_sizes, int n_in,
                              void* d_out, int out_size) {
    const float* x = (const float*)d_in[0];
    float* out = (float*)d_out;
    softscan_kernel<<<BATCH, THREADS>>>(x, out);   /* 32 CTAs, no inter-CTA deps */
}

// round 17
// speedup vs baseline: 1.4822x; 1.4822x over previous
#include <cuda_runtime.h>

#define BATCH   32
#define TSTEPS  1024
#define COLS    2048
#define SPLIT   4              /* CTAs per batch row                       */
#define THREADS 128            /* 4 warps, one per SMSP                    */
#define WARPS   4
#define ROW4    (COLS / 4)     /* 512 float4 per row                       */
#define ROW2    (COLS / 2)     /* 1024 float2 per row                      */
#define TCHUNK  64             /* steps per chunk = halo width             */
#define NCHUNK  16             /* 1024 / 64                                */
#define DPF     8              /* x prefetch depth (time steps)            */

/* Cross-CTA halo: per (batch,cta,chunk) slot of 16 float4 (64 floats). */
__device__ float4   g_halo[BATCH * SPLIT * NCHUNK * 16];   /* 512 KB */
__device__ unsigned g_flag[BATCH * SPLIT];                 /* monotonic chunk counters */

__device__ __forceinline__ unsigned ld_acq32(const unsigned* p) {
    unsigned v;
    asm volatile("ld.acquire.gpu.global.b32 %0, [%1];" : "=r"(v) : "l"(p) : "memory");
    return v;
}
__device__ __forceinline__ void st_rel32(unsigned* p, unsigned v) {
    asm volatile("st.release.gpu.global.b32 [%0], %1;" :: "l"(p), "r"(v) : "memory");
}

__device__ __forceinline__ float smix(float a, float b) {
    float d = a - b;
    float e = __expf(-d);                  /* MUFU.EX2 */
    float p = __fdividef(1.0f, 1.0f + e);  /* MUFU.RCP */
    return fmaf(p, d, b);                  /* b + p*(a-b) */
}

__global__ __launch_bounds__(THREADS, 1)
void softscan_kernel(const float* __restrict__ x, float* __restrict__ out) {
    const int s    = blockIdx.x;
    const int b    = blockIdx.y;
    const int tid  = threadIdx.x;
    const int lane = tid & 31;
    const int warp = tid >> 5;

    /* warp owns 128 cols starting at W0; carries 64-col halo [W0-64, W0) */
    const int W0 = (s * WARPS + warp) * 128;
    const bool firstcol = (s == 0) && (warp == 0) && (lane == 0);

    __shared__ float4 sm_halo[WARPS - 1][16];   /* intra-CTA boundary exchange */

    const float* xrow = x   + (size_t)b * TSTEPS * COLS;
    float*       orow = out + (size_t)b * TSTEPS * COLS;

    const float4* x4  = (const float4*)xrow + (W0 / 4 + lane);   /* own cols  */
    float4*       o4  = (float4*)      orow + (W0 / 4 + lane);
    int hcol = W0 - 64 + 2 * lane; if (hcol < 0) hcol = 0;       /* clamp (CTA0/warp0: halo unused) */
    const float2* xh2 = (const float2*)xrow + (hcol / 2);        /* halo cols */

    /* ---- state at t = 0 ---- */
    float4 c = __ldcs(x4);                  /* own carries  */
    __stcs(o4, c);
    float2 hv = __ldcs(xh2);
    float h0 = hv.x, h1 = hv.y;             /* halo carries */

    /* x prefetch ring */
    float4 bo[DPF]; float2 bh[DPF];
    #pragma unroll
    for (int k = 0; k < DPF; ++k) {
        bo[k] = __ldcs(x4  + (size_t)(k + 1) * ROW4);
        bh[k] = __ldcs(xh2 + (size_t)(k + 1) * ROW2);
    }

    const int my_id = b * SPLIT + s;

    for (int ch = 0; ch < NCHUNK; ++ch) {
        if (ch > 0) {
            /* ---- boundary: refresh halo with exact state at t = 64*ch ---- */
            /* produce downstream FIRST (unblocks the chain) */
            if (warp == WARPS - 1 && s != SPLIT - 1) {
                if (lane >= 16)
                    g_halo[((size_t)my_id * NCHUNK + ch) * 16 + (lane - 16)] = c;
                __syncwarp();
                if (lane == 0) st_rel32(&g_flag[my_id], (unsigned)ch);
            }
            /* intra-CTA: warp w gives its top 64 cols to warp w+1 */
            if (warp < WARPS - 1 && lane >= 16)
                sm_halo[warp][lane - 16] = c;
            __syncthreads();
            if (warp > 0) {
                const float* p = (const float*)&sm_halo[warp - 1][0];
                h0 = p[2 * lane]; h1 = p[2 * lane + 1];
            } else if (s > 0) {
                const unsigned* f = &g_flag[my_id - 1];
                while (ld_acq32(f) < (unsigned)ch) { }
                const float* p = (const float*)&g_halo[((size_t)(my_id - 1) * NCHUNK + ch) * 16];
                h0 = p[2 * lane]; h1 = p[2 * lane + 1];
            }
            __syncthreads();   /* protect sm_halo against fast-warp overwrite */
        }

        /* ---- 64 communication-free steps (warps free-run) ---- */
        const int t0 = ch * TCHUNK;
        for (int kk = 0; kk < TCHUNK; kk += DPF) {
            #pragma unroll
            for (int j = 0; j < DPF; ++j) {
                const int t = t0 + kk + j + 1;
                if (t >= TSTEPS) break;            /* only last chunk (63 steps) */
                const int slot = (kk + j) & 7;

                float4 xv = bo[slot]; float2 xh = bh[slot];
                int pf = t + DPF; if (pf > TSTEPS - 1) pf = TSTEPS - 1;
                bo[slot] = __ldcs(x4  + (size_t)pf * ROW4);
                bh[slot] = __ldcs(xh2 + (size_t)pf * ROW2);

                /* neighbor values from step t-1 (old registers) */
                float oleft = __shfl_up_sync(0xffffffffu, c.w, 1);
                float hleft = __shfl_up_sync(0xffffffffu, h1, 1);
                float wrap  = __shfl_sync  (0xffffffffu, h1, 31);
                if (lane == 0) oleft = wrap;   /* own col 0's left = halo col 63 */

                /* halo update (garbage propagates 1 col/step, stays in halo) */
                float nh0 = xh.x + smix(h0, hleft);
                float nh1 = xh.y + smix(h1, h0);
                /* own update */
                float4 nc;
                nc.x = firstcol ? (xv.x + c.x) : (xv.x + smix(c.x, oleft));
                nc.y = xv.y + smix(c.y, c.x);
                nc.z = xv.z + smix(c.z, c.y);
                nc.w = xv.w + smix(c.w, c.z);
                h0 = nh0; h1 = nh1; c = nc;

                __stcs(o4 + (size_t)t * ROW4, c);   /* owners store; halo never stored */
            }
        }
    }
}

extern "C" void kernel_launch(void* const* d_in, const int* in_sizes, int n_in,
                              void* d_out, int out_size) {
    const float* x = (const float*)d_in[0];
    float* out = (float*)d_out;

    /* Reset chunk flags each launch (captured memset node -> replay-safe). */
    void* flag_ptr = nullptr;
    cudaGetSymbolAddress(&flag_ptr, g_flag);
    cudaMemsetAsync(flag_ptr, 0, sizeof(unsigned) * BATCH * SPLIT, 0);

    dim3 grid(SPLIT, BATCH);   /* 128 CTAs: single wave, flag chain deadlock-free */
    softscan_kernel<<<grid, THREADS>>>(x, out);
}